// round 15
// baseline (speedup 1.0000x reference)
#include <cuda_runtime.h>
#include <cuda_bf16.h>
#include <cuda_fp16.h>
#include <cstdint>
#include <stdint.h>
#include <math.h>

#define SB    2048
#define DIMD  2048
#define BATCH 2
#define NH    16
#define NKVH  4
#define HD    128
#define KVF   1024
#define ROWS  (BATCH*SB)   // 4096

// ---------------- scratch (device globals: allocation-free) ----------------
__device__ __half g_q16 [(size_t)ROWS*DIMD];
__device__ __half g_kv16[(size_t)ROWS*KVF];
__device__ __half g_xq16[(size_t)ROWS*DIMD];
__device__ __half g_x16 [(size_t)ROWS*DIMD];
__device__ __half g_at16[(size_t)ROWS*DIMD];
__device__ __half g_wq16 [(size_t)DIMD*DIMD];
__device__ __half g_wkv16[(size_t)KVF *DIMD];
__device__ __half g_wo16 [(size_t)DIMD*DIMD];

// ---------------- helpers ----------------
__device__ __forceinline__ uint32_t pack_h2(__half a, __half b) {
    __half2 t; t.x = a; t.y = b;
    return *(uint32_t*)&t;
}

// ---------------- kernel 1: complexity gate -> fp16 xq AND fp16 x ----------
__global__ __launch_bounds__(256) void gate_h_kernel(const float* __restrict__ x,
                                                     __half* __restrict__ xqh,
                                                     __half* __restrict__ xh) {
    int row = blockIdx.x;
    const float* xr = x + (size_t)row * DIMD;
    float s = 0.f;
    for (int c = threadIdx.x; c < DIMD; c += 256) s += fabsf(xr[c]);
    __shared__ float red[256];
    red[threadIdx.x] = s; __syncthreads();
    for (int off = 128; off > 0; off >>= 1) {
        if (threadIdx.x < off) red[threadIdx.x] += red[threadIdx.x + off];
        __syncthreads();
    }
    float cw = 1.f / (1.f + __expf(-red[0]));
    size_t base = (size_t)row * DIMD;
    for (int c = threadIdx.x; c < DIMD; c += 256) {
        float v = xr[c];
        xh [base + c] = __float2half_rn(v);
        xqh[base + c] = __float2half_rn(v * cw);
    }
}

// ---------------- transpose W[K][N] -> T[N][K], single fp16 ----------------
__global__ __launch_bounds__(256) void transpose_h_kernel(
    const float* __restrict__ W, __half* __restrict__ T, int K, int N) {
    __shared__ float tile[32][33];
    int n0 = blockIdx.x * 32, k0 = blockIdx.y * 32;
    int tx = threadIdx.x, ty = threadIdx.y;
#pragma unroll
    for (int r = ty; r < 32; r += 8)
        tile[r][tx] = W[(size_t)(k0 + r) * N + n0 + tx];
    __syncthreads();
#pragma unroll
    for (int r = ty; r < 32; r += 8)
        T[(size_t)(n0 + r) * K + k0 + tx] = __float2half_rn(tile[tx][r]);
}

// ---------------- mma primitives ----------------
__device__ __forceinline__ void cp16(uint32_t dst, const void* src) {
    asm volatile("cp.async.cg.shared.global [%0], [%1], 16;\n" :: "r"(dst), "l"(src));
}
__device__ __forceinline__ void cp_commit() { asm volatile("cp.async.commit_group;\n"); }
__device__ __forceinline__ void cp_wait1() { asm volatile("cp.async.wait_group 1;\n"); }
__device__ __forceinline__ void cp_wait0() { asm volatile("cp.async.wait_group 0;\n"); }
__device__ __forceinline__ void ldsm4(uint32_t& r0, uint32_t& r1, uint32_t& r2, uint32_t& r3,
                                      uint32_t addr) {
    asm volatile("ldmatrix.sync.aligned.m8n8.x4.shared.b16 {%0,%1,%2,%3}, [%4];\n"
                 : "=r"(r0), "=r"(r1), "=r"(r2), "=r"(r3) : "r"(addr));
}
__device__ __forceinline__ void ldsm4t(uint32_t& r0, uint32_t& r1, uint32_t& r2, uint32_t& r3,
                                       uint32_t addr) {
    asm volatile("ldmatrix.sync.aligned.m8n8.x4.trans.shared.b16 {%0,%1,%2,%3}, [%4];\n"
                 : "=r"(r0), "=r"(r1), "=r"(r2), "=r"(r3) : "r"(addr));
}
__device__ __forceinline__ void mma_f16(float* d, uint32_t a0, uint32_t a1, uint32_t a2,
                                        uint32_t a3, uint32_t b0, uint32_t b1) {
    asm volatile("mma.sync.aligned.m16n8k16.row.col.f32.f16.f16.f32 "
                 "{%0,%1,%2,%3}, {%4,%5,%6,%7}, {%8,%9}, {%0,%1,%2,%3};\n"
                 : "+f"(d[0]), "+f"(d[1]), "+f"(d[2]), "+f"(d[3])
                 : "r"(a0), "r"(a1), "r"(a2), "r"(a3), "r"(b0), "r"(b1));
}

// ---------------- shared tile constants (256x128 block, 8 warps 64x64) ------
#define SROWB 80
#define ABUF  (256*SROWB)        // 20480 B
#define BBUF  (128*SROWB)        // 10240 B
#define STAGE1B (ABUF + BBUF)    // A|B = 30720
#define GEMM3S_SMEM (3*STAGE1B)  // 92160 (3-stage)

#define GEMM_ISSUE(s) do {                                                       \
    const uint32_t so = (uint32_t)(((s) % 3) * STAGE1B);                         \
    const size_t off = (size_t)(s) * 32;                                         \
    _Pragma("unroll")                                                            \
    for (int c = 0; c < 4; c++) cp16(aD + so + c * 16, A + aG + off + c * 8);    \
    cp16(bD + so,      B + bG + off);                                            \
    cp16(bD + so + 16, B + bG + off + 8);                                        \
    cp_commit();                                                                 \
} while (0)

// ---------------- fused Q+KV fp16 GEMM: fp16 out, 3-stage --------------------
__global__ __launch_bounds__(256, 1) void gemm_qkv_kernel(
    const __half* __restrict__ Aq, const __half* __restrict__ Ax,
    const __half* __restrict__ Bq, const __half* __restrict__ Bkv,
    __half* __restrict__ Cq, __half* __restrict__ Ckv) {
    extern __shared__ char smem[];
    const uint32_t sb = (uint32_t)__cvta_generic_to_shared(smem);
    const int tid = threadIdx.x;
    const int lane = tid & 31, wid = tid >> 5;
    const int warpM = wid >> 1, warpN = wid & 1;

    const bool isQ = blockIdx.x < 16;
    const __half* A = isQ ? Aq : Ax;
    const __half* B = isQ ? Bq : Bkv;
    __half* C = isQ ? Cq : Ckv;
    const int N = isQ ? DIMD : KVF;
    const int K = DIMD;
    const int mBlk = blockIdx.y * 256;
    const int nBlk = (isQ ? blockIdx.x : (blockIdx.x - 16)) * 128;

    const size_t aG = (size_t)(mBlk + tid) * K;
    const int brow = tid >> 1, bc0 = (tid & 1) * 2;
    const size_t bG = (size_t)(nBlk + brow) * K + bc0 * 8;
    const uint32_t aD = sb + tid * SROWB;
    const uint32_t bD = sb + ABUF + brow * SROWB + bc0 * 16;

    const int aRow = warpM * 64 + (lane & 7) + ((lane >> 3) & 1) * 8;
    const uint32_t aLd = aRow * SROWB + (lane >> 4) * 16;
    const int bRow = warpN * 64 + (lane & 7) + (lane >> 4) * 8;
    const uint32_t bLd = bRow * SROWB + ((lane >> 3) & 1) * 16;

    float acc[4][8][4];
#pragma unroll
    for (int i = 0; i < 4; i++)
#pragma unroll
        for (int j = 0; j < 8; j++)
#pragma unroll
            for (int r = 0; r < 4; r++) acc[i][j][r] = 0.f;

    const int nkt = K / 32;
    GEMM_ISSUE(0);
    GEMM_ISSUE(1);

    for (int kt = 0; kt < nkt; kt++) {
        if (kt < nkt - 1) cp_wait1(); else cp_wait0();
        __syncthreads();
        if (kt + 2 < nkt) GEMM_ISSUE(kt + 2);

        const uint32_t base = sb + (uint32_t)((kt % 3) * STAGE1B);
#pragma unroll
        for (int kkB = 0; kkB < 64; kkB += 32) {
            uint32_t bh[16];
#pragma unroll
            for (int g = 0; g < 4; g++)
                ldsm4(bh[4*g], bh[4*g+1], bh[4*g+2], bh[4*g+3],
                      base + ABUF + bLd + kkB + (uint32_t)(g * 16 * SROWB));
#pragma unroll
            for (int i = 0; i < 4; i++) {
                uint32_t ah[4];
                ldsm4(ah[0], ah[1], ah[2], ah[3],
                      base + aLd + (uint32_t)(i * 16 * SROWB) + kkB);
#pragma unroll
                for (int j = 0; j < 8; j++)
                    mma_f16(acc[i][j], ah[0], ah[1], ah[2], ah[3], bh[2*j], bh[2*j+1]);
            }
        }
    }

#pragma unroll
    for (int i = 0; i < 4; i++) {
#pragma unroll
        for (int j = 0; j < 8; j++) {
            int rg = mBlk + warpM * 64 + i * 16 + (lane >> 2);
            int cg = nBlk + warpN * 64 + j * 8 + (lane & 3) * 2;
            *(uint32_t*)(C + (size_t)rg * N + cg) =
                pack_h2(__float2half_rn(acc[i][j][0]), __float2half_rn(acc[i][j][1]));
            *(uint32_t*)(C + (size_t)(rg + 8) * N + cg) =
                pack_h2(__float2half_rn(acc[i][j][2]), __float2half_rn(acc[i][j][3]));
        }
    }
}

// ---------------- Wo GEMM: fp32 out + bias, 3-stage --------------------------
__global__ __launch_bounds__(256, 1) void gemm_out_kernel(
    const __half* __restrict__ A, const __half* __restrict__ B,
    const float* __restrict__ bias, float* __restrict__ C) {
    extern __shared__ char smem[];
    const uint32_t sb = (uint32_t)__cvta_generic_to_shared(smem);
    const int tid = threadIdx.x;
    const int lane = tid & 31, wid = tid >> 5;
    const int warpM = wid >> 1, warpN = wid & 1;
    const int N = DIMD, K = DIMD;
    const int mBlk = blockIdx.y * 256, nBlk = blockIdx.x * 128;

    const size_t aG = (size_t)(mBlk + tid) * K;
    const int brow = tid >> 1, bc0 = (tid & 1) * 2;
    const size_t bG = (size_t)(nBlk + brow) * K + bc0 * 8;
    const uint32_t aD = sb + tid * SROWB;
    const uint32_t bD = sb + ABUF + brow * SROWB + bc0 * 16;

    const int aRow = warpM * 64 + (lane & 7) + ((lane >> 3) & 1) * 8;
    const uint32_t aLd = aRow * SROWB + (lane >> 4) * 16;
    const int bRow = warpN * 64 + (lane & 7) + (lane >> 4) * 8;
    const uint32_t bLd = bRow * SROWB + ((lane >> 3) & 1) * 16;

    float acc[4][8][4];
#pragma unroll
    for (int i = 0; i < 4; i++)
#pragma unroll
        for (int j = 0; j < 8; j++)
#pragma unroll
            for (int r = 0; r < 4; r++) acc[i][j][r] = 0.f;

    const int nkt = K / 32;
    GEMM_ISSUE(0);
    GEMM_ISSUE(1);

    for (int kt = 0; kt < nkt; kt++) {
        if (kt < nkt - 1) cp_wait1(); else cp_wait0();
        __syncthreads();
        if (kt + 2 < nkt) GEMM_ISSUE(kt + 2);

        const uint32_t base = sb + (uint32_t)((kt % 3) * STAGE1B);
#pragma unroll
        for (int kkB = 0; kkB < 64; kkB += 32) {
            uint32_t bh[16];
#pragma unroll
            for (int g = 0; g < 4; g++)
                ldsm4(bh[4*g], bh[4*g+1], bh[4*g+2], bh[4*g+3],
                      base + ABUF + bLd + kkB + (uint32_t)(g * 16 * SROWB));
#pragma unroll
            for (int i = 0; i < 4; i++) {
                uint32_t ah[4];
                ldsm4(ah[0], ah[1], ah[2], ah[3],
                      base + aLd + (uint32_t)(i * 16 * SROWB) + kkB);
#pragma unroll
                for (int j = 0; j < 8; j++)
                    mma_f16(acc[i][j], ah[0], ah[1], ah[2], ah[3], bh[2*j], bh[2*j+1]);
            }
        }
    }

#pragma unroll
    for (int i = 0; i < 4; i++) {
#pragma unroll
        for (int j = 0; j < 8; j++) {
            int rg = mBlk + warpM * 64 + i * 16 + (lane >> 2);
            int cg = nBlk + warpN * 64 + j * 8 + (lane & 3) * 2;
            float b0 = bias[cg], b1 = bias[cg + 1];
            *(float2*)(C + (size_t)rg * N + cg) =
                make_float2(acc[i][j][0] + b0, acc[i][j][1] + b1);
            *(float2*)(C + (size_t)(rg + 8) * N + cg) =
                make_float2(acc[i][j][2] + b0, acc[i][j][3] + b1);
        }
    }
}

// ---------------- vmean: global query rows (i<64) -> fp16 at ----------------
__global__ __launch_bounds__(1024) void vmean_kernel(const __half* __restrict__ kv,
                                                     __half* __restrict__ at16) {
    int b = blockIdx.x >> 2, kvh = blockIdx.x & 3;
    int d = threadIdx.x & 127;
    int c = threadIdx.x >> 7;
    const __half* v = kv + (size_t)b * SB * KVF + NKVH * HD + kvh * HD + d;
    float s = 0.f;
    int j0 = c * 256;
#pragma unroll 8
    for (int j = j0; j < j0 + 256; j++) s += __half2float(v[(size_t)j * KVF]);
    __shared__ float red[8][128];
    red[c][d] = s;
    __syncthreads();
    if (c == 0) {
        float t = 0.f;
#pragma unroll
        for (int u = 0; u < 8; u++) t += red[u][d];
        __half th = __float2half_rn(t * (1.0f / 2048.0f));
        for (int hh = 0; hh < 4; hh++) {
            int h = kvh * 4 + hh;
            for (int i = 0; i < 64; i++)
                at16[((size_t)(b * SB) + i) * DIMD + h * HD + d] = th;
        }
    }
}

// ---------------- fp16 flash attention: 2 heads/block, cp.async KV pipeline --
// smem (fp16, 136 halfs/row, 17408 B/tile): Q0 | Q1 | K0 | V0 | K1 | V1
#define TILEB 17408
#define AQ0   0
#define AKV(s) (2*TILEB + (s)*2*TILEB)      // K at AKV, V at AKV+TILEB
#define ATTN_SMEM_BYTES (6*TILEB)           // 104448

__global__ __launch_bounds__(256) void attn_mma_kernel(
    const __half* __restrict__ q, const __half* __restrict__ kv,
    __half* __restrict__ at16) {
    extern __shared__ char asmem[];
    __half* sB = (__half*)asmem;
    const uint32_t sb = (uint32_t)__cvta_generic_to_shared(asmem);

    const int tid = threadIdx.x;
    const int lane = tid & 31, w = tid >> 5;
    const int hw = w >> 2, w4 = w & 3;       // head-in-pair, warp-in-head
    const int i0 = 64 + blockIdx.x * 64;
    const int h  = blockIdx.y * 2 + hw;
    const int b  = blockIdx.z;
    const int kvh = blockIdx.y >> 1;
    const float slope = exp2f(-0.5f * (float)(h + 1));
    const float scale = 0.08838834764831845f;

    const __half* kbase = kv + ((size_t)b * SB * KVF) + kvh * HD;
    const __half* vbase = kbase + NKVH * HD;

    // load both heads' Q tiles (fp16 straight copies)
#pragma unroll
    for (int it = 0; it < 8; it++) {
        int flat = it * 2048 + tid * 8;      // 16384 halfs over 2 tiles
        int tile = flat >> 13;
        int r = (flat >> 7) & 63, c = flat & 127;
        int ht = blockIdx.y * 2 + tile;
        *(uint4*)(sB + tile * (TILEB/2) + r * 136 + c) =
            *(const uint4*)(q + ((size_t)(b * SB + i0 + r) * DIMD) + ht * HD + c);
    }

    // per-thread cp.async mapping for K/V tiles (4 chunks each of 16B)
    const int kcBase = tid * 4;              // chunk ids 0..1023

    const uint32_t aOff = (uint32_t)((w4 * 16 + (lane & 7) + ((lane >> 3) & 1) * 8) * 272
                                     + (lane >> 4) * 16) + (uint32_t)(hw * TILEB);
    const uint32_t bRowOff = (uint32_t)(((lane & 7) + (lane >> 4) * 8) * 272
                                        + ((lane >> 3) & 1) * 16);
    const uint32_t vOff = (uint32_t)(((lane & 7) + ((lane >> 3) & 1) * 8) * 272
                                     + (lane >> 4) * 16);

    const int gi0 = i0 + w4 * 16 + (lane >> 2);
    const int gi1 = gi0 + 8;
    const int cb  = (lane & 3) * 2;
    float m0 = -INFINITY, m1 = -INFINITY, l0 = 0.f, l1 = 0.f;

    float o[16][4];
#pragma unroll
    for (int f = 0; f < 16; f++)
#pragma unroll
        for (int r = 0; r < 4; r++) o[f][r] = 0.f;

    // first valid tile
    int j0 = 64;
    while (j0 < SB) {
        int md = max(abs(i0 - (j0 + 63)), abs((i0 + 63) - j0));
        if (md > 256) break;
        j0 += 64;
    }
    int cur = 0;
    if (j0 < SB) {
#pragma unroll
        for (int c = 0; c < 4; c++) {
            int idx = kcBase + c;
            int r = idx >> 4, cc = idx & 15;
            cp16(sb + AKV(0) + (uint32_t)(r * 272 + cc * 16),
                 kbase + (size_t)(j0 + r) * KVF + cc * 8);
            cp16(sb + AKV(0) + TILEB + (uint32_t)(r * 272 + cc * 16),
                 vbase + (size_t)(j0 + r) * KVF + cc * 8);
        }
        cp_commit();
    }

    while (j0 < SB) {
        // next valid tile
        int j1 = j0 + 64;
        while (j1 < SB) {
            int md = max(abs(i0 - (j1 + 63)), abs((i0 + 63) - j1));
            if (md > 256) break;
            j1 += 64;
        }
        if (j1 < SB) {
            const int nxt = cur ^ 1;
#pragma unroll
            for (int c = 0; c < 4; c++) {
                int idx = kcBase + c;
                int r = idx >> 4, cc = idx & 15;
                cp16(sb + AKV(nxt) + (uint32_t)(r * 272 + cc * 16),
                     kbase + (size_t)(j1 + r) * KVF + cc * 8);
                cp16(sb + AKV(nxt) + TILEB + (uint32_t)(r * 272 + cc * 16),
                     vbase + (size_t)(j1 + r) * KVF + cc * 8);
            }
            cp_commit();
            cp_wait1();
        } else {
            cp_wait0();
        }
        __syncthreads();   // tile cur visible to all; Q visible (first iter)

        const uint32_t AK = AKV(cur), AV = AKV(cur) + TILEB;

        // ---- S = Q K^T ----
        float sacc[8][4];
#pragma unroll
        for (int j = 0; j < 8; j++)
#pragma unroll
            for (int r = 0; r < 4; r++) sacc[j][r] = 0.f;

#pragma unroll
        for (int kk = 0; kk < 8; kk++) {
            uint32_t qf[4];
            ldsm4(qf[0], qf[1], qf[2], qf[3], sb + AQ0 + aOff + kk * 32);
#pragma unroll
            for (int g = 0; g < 4; g++) {
                uint32_t kf[4];
                ldsm4(kf[0], kf[1], kf[2], kf[3],
                      sb + AK + bRowOff + (uint32_t)(g * 16 * 272) + kk * 32);
                mma_f16(sacc[2*g],   qf[0], qf[1], qf[2], qf[3], kf[0], kf[1]);
                mma_f16(sacc[2*g+1], qf[0], qf[1], qf[2], qf[3], kf[2], kf[3]);
            }
        }

        // ---- mask + ALiBi + online softmax (fp32) ----
        float tmax0 = -INFINITY, tmax1 = -INFINITY;
#pragma unroll
        for (int j = 0; j < 8; j++) {
            int gj = j0 + j * 8 + cb;
#pragma unroll
            for (int e = 0; e < 4; e++) {
                int gi = (e < 2) ? gi0 : gi1;
                int dist = abs(gi - (gj + (e & 1)));
                float val = (dist <= 256) ? -1e9f
                                          : (sacc[j][e] * scale - slope * (float)dist);
                sacc[j][e] = val;
                if (e < 2) tmax0 = fmaxf(tmax0, val);
                else       tmax1 = fmaxf(tmax1, val);
            }
        }
        tmax0 = fmaxf(tmax0, __shfl_xor_sync(0xffffffffu, tmax0, 1));
        tmax0 = fmaxf(tmax0, __shfl_xor_sync(0xffffffffu, tmax0, 2));
        tmax1 = fmaxf(tmax1, __shfl_xor_sync(0xffffffffu, tmax1, 1));
        tmax1 = fmaxf(tmax1, __shfl_xor_sync(0xffffffffu, tmax1, 2));

        float mn0 = fmaxf(m0, tmax0), mn1 = fmaxf(m1, tmax1);
        float f0 = __expf(m0 - mn0), f1 = __expf(m1 - mn1);
        float rs0 = 0.f, rs1 = 0.f;
#pragma unroll
        for (int j = 0; j < 8; j++) {
            float p0 = __expf(sacc[j][0] - mn0);
            float p1 = __expf(sacc[j][1] - mn0);
            float p2 = __expf(sacc[j][2] - mn1);
            float p3 = __expf(sacc[j][3] - mn1);
            sacc[j][0] = p0; sacc[j][1] = p1; sacc[j][2] = p2; sacc[j][3] = p3;
            rs0 += p0 + p1; rs1 += p2 + p3;
        }
        rs0 += __shfl_xor_sync(0xffffffffu, rs0, 1);
        rs0 += __shfl_xor_sync(0xffffffffu, rs0, 2);
        rs1 += __shfl_xor_sync(0xffffffffu, rs1, 1);
        rs1 += __shfl_xor_sync(0xffffffffu, rs1, 2);
        l0 = l0 * f0 + rs0; l1 = l1 * f1 + rs1;
        m0 = mn0; m1 = mn1;

#pragma unroll
        for (int f = 0; f < 16; f++) {
            o[f][0] *= f0; o[f][1] *= f0;
            o[f][2] *= f1; o[f][3] *= f1;
        }

        // ---- O += P V ----
#pragma unroll
        for (int kk = 0; kk < 4; kk++) {
            uint32_t pF[4];
            pF[0] = pack_h2(__float2half_rn(sacc[2*kk][0]),   __float2half_rn(sacc[2*kk][1]));
            pF[1] = pack_h2(__float2half_rn(sacc[2*kk][2]),   __float2half_rn(sacc[2*kk][3]));
            pF[2] = pack_h2(__float2half_rn(sacc[2*kk+1][0]), __float2half_rn(sacc[2*kk+1][1]));
            pF[3] = pack_h2(__float2half_rn(sacc[2*kk+1][2]), __float2half_rn(sacc[2*kk+1][3]));
#pragma unroll
            for (int g = 0; g < 8; g++) {
                uint32_t vh[4];
                ldsm4t(vh[0], vh[1], vh[2], vh[3],
                       sb + AV + vOff + (uint32_t)(kk * 16 * 272) + (uint32_t)(g * 32));
                mma_f16(o[2*g],   pF[0], pF[1], pF[2], pF[3], vh[0], vh[1]);
                mma_f16(o[2*g+1], pF[0], pF[1], pF[2], pF[3], vh[2], vh[3]);
            }
        }

        __syncthreads();   // all warps done with tile cur before it is reloaded
        j0 = j1;
        cur ^= 1;
    }

    // epilogue: divide by l, write single fp16
    float inv0 = 1.f / l0, inv1 = 1.f / l1;
    size_t row0 = (size_t)(b * SB) + gi0;
    size_t row1 = (size_t)(b * SB) + gi1;
#pragma unroll
    for (int f = 0; f < 16; f++) {
        int cg = h * HD + f * 8 + cb;
        *(uint32_t*)(at16 + row0 * DIMD + cg) =
            pack_h2(__float2half_rn(o[f][0] * inv0), __float2half_rn(o[f][1] * inv0));
        *(uint32_t*)(at16 + row1 * DIMD + cg) =
            pack_h2(__float2half_rn(o[f][2] * inv1), __float2half_rn(o[f][3] * inv1));
    }
}

// ---------------- launcher ----------------
extern "C" void kernel_launch(void* const* d_in, const int* in_sizes, int n_in,
                              void* d_out, int out_size) {
    (void)in_sizes; (void)n_in; (void)out_size;
    const float* x   = (const float*)d_in[0];
    const float* Wq  = (const float*)d_in[1];
    const float* Wkv = (const float*)d_in[2];
    const float* Wo  = (const float*)d_in[3];
    const float* bo  = (const float*)d_in[4];
    float* out = (float*)d_out;

    __half *q16, *kv16, *xq16, *x16, *at16, *wq16, *wkv16, *wo16;
    cudaGetSymbolAddress((void**)&q16,   g_q16);
    cudaGetSymbolAddress((void**)&kv16,  g_kv16);
    cudaGetSymbolAddress((void**)&xq16,  g_xq16);
    cudaGetSymbolAddress((void**)&x16,   g_x16);
    cudaGetSymbolAddress((void**)&at16,  g_at16);
    cudaGetSymbolAddress((void**)&wq16,  g_wq16);
    cudaGetSymbolAddress((void**)&wkv16, g_wkv16);
    cudaGetSymbolAddress((void**)&wo16,  g_wo16);

    cudaFuncSetAttribute(attn_mma_kernel, cudaFuncAttributeMaxDynamicSharedMemorySize,
                         ATTN_SMEM_BYTES);
    cudaFuncSetAttribute(gemm_qkv_kernel, cudaFuncAttributeMaxDynamicSharedMemorySize,
                         GEMM3S_SMEM);
    cudaFuncSetAttribute(gemm_out_kernel, cudaFuncAttributeMaxDynamicSharedMemorySize,
                         GEMM3S_SMEM);

    // gating + operand prep
    gate_h_kernel<<<ROWS, 256>>>(x, xq16, x16);
    transpose_h_kernel<<<dim3(DIMD/32, DIMD/32), dim3(32, 8)>>>(Wq,  wq16,  DIMD, DIMD);
    transpose_h_kernel<<<dim3(KVF/32,  DIMD/32), dim3(32, 8)>>>(Wkv, wkv16, DIMD, KVF);
    transpose_h_kernel<<<dim3(DIMD/32, DIMD/32), dim3(32, 8)>>>(Wo,  wo16,  DIMD, DIMD);

    // fused Q + KV projection (fp16 outputs)
    gemm_qkv_kernel<<<dim3(24, ROWS/256), 256, GEMM3S_SMEM>>>(
        xq16, x16, wq16, wkv16, q16, kv16);

    // attention (2 heads per block, fp16 in/out)
    vmean_kernel<<<BATCH * NKVH, 1024>>>(kv16, at16);
    dim3 ga(31, NH / 2, BATCH);
    attn_mma_kernel<<<ga, 256, ATTN_SMEM_BYTES>>>(q16, kv16, at16);

    // output projection (fp32 out + bias)
    gemm_out_kernel<<<dim3(DIMD/128, ROWS/256), 256, GEMM3S_SMEM>>>(
        at16, wo16, bo, out);
}

// round 16
// speedup vs baseline: 1.0630x; 1.0630x over previous
#include <cuda_runtime.h>
#include <cuda_bf16.h>
#include <cuda_fp16.h>
#include <cstdint>
#include <stdint.h>
#include <math.h>

#define SB    2048
#define DIMD  2048
#define BATCH 2
#define NH    16
#define NKVH  4
#define HD    128
#define KVF   1024
#define ROWS  (BATCH*SB)   // 4096

// ---------------- scratch (device globals: allocation-free) ----------------
__device__ __half g_q16 [(size_t)ROWS*DIMD];
__device__ __half g_kv16[(size_t)ROWS*KVF];
__device__ __half g_xq16[(size_t)ROWS*DIMD];
__device__ __half g_x16 [(size_t)ROWS*DIMD];
__device__ __half g_at16[(size_t)ROWS*DIMD];
__device__ __half g_wq16 [(size_t)DIMD*DIMD];
__device__ __half g_wkv16[(size_t)KVF *DIMD];
__device__ __half g_wo16 [(size_t)DIMD*DIMD];

// ---------------- helpers ----------------
__device__ __forceinline__ uint32_t pack_h2(__half a, __half b) {
    __half2 t; t.x = a; t.y = b;
    return *(uint32_t*)&t;
}

// ---------------- kernel 1: complexity gate -> fp16 xq AND fp16 x ----------
__global__ __launch_bounds__(256) void gate_h_kernel(const float* __restrict__ x,
                                                     __half* __restrict__ xqh,
                                                     __half* __restrict__ xh) {
    int row = blockIdx.x;
    const float* xr = x + (size_t)row * DIMD;
    float s = 0.f;
    for (int c = threadIdx.x; c < DIMD; c += 256) s += fabsf(xr[c]);
    __shared__ float red[256];
    red[threadIdx.x] = s; __syncthreads();
    for (int off = 128; off > 0; off >>= 1) {
        if (threadIdx.x < off) red[threadIdx.x] += red[threadIdx.x + off];
        __syncthreads();
    }
    float cw = 1.f / (1.f + __expf(-red[0]));
    size_t base = (size_t)row * DIMD;
    for (int c = threadIdx.x; c < DIMD; c += 256) {
        float v = xr[c];
        xh [base + c] = __float2half_rn(v);
        xqh[base + c] = __float2half_rn(v * cw);
    }
}

// ------- fused transpose: Wq|Wkv|Wo [K][N] -> T[N][K], single fp16 ---------
__global__ __launch_bounds__(256) void transpose_all_kernel(
    const float* __restrict__ Wq, const float* __restrict__ Wkv,
    const float* __restrict__ Wo,
    __half* __restrict__ Tq, __half* __restrict__ Tkv, __half* __restrict__ To) {
    __shared__ float tile[32][33];
    const float* W; __half* T; int N;
    int bx = blockIdx.x;
    if (bx < 64)      { W = Wq;  T = Tq;  N = DIMD; }
    else if (bx < 96) { W = Wkv; T = Tkv; N = KVF;  bx -= 64; }
    else              { W = Wo;  T = To;  N = DIMD; bx -= 96; }
    const int K = DIMD;
    int n0 = bx * 32, k0 = blockIdx.y * 32;
    int tx = threadIdx.x, ty = threadIdx.y;
#pragma unroll
    for (int r = ty; r < 32; r += 8)
        tile[r][tx] = W[(size_t)(k0 + r) * N + n0 + tx];
    __syncthreads();
#pragma unroll
    for (int r = ty; r < 32; r += 8)
        T[(size_t)(n0 + r) * K + k0 + tx] = __float2half_rn(tile[tx][r]);
}

// ---------------- mma primitives ----------------
__device__ __forceinline__ void cp16(uint32_t dst, const void* src) {
    asm volatile("cp.async.cg.shared.global [%0], [%1], 16;\n" :: "r"(dst), "l"(src));
}
__device__ __forceinline__ void cp_commit() { asm volatile("cp.async.commit_group;\n"); }
__device__ __forceinline__ void cp_wait1() { asm volatile("cp.async.wait_group 1;\n"); }
__device__ __forceinline__ void cp_wait0() { asm volatile("cp.async.wait_group 0;\n"); }
__device__ __forceinline__ void ldsm4(uint32_t& r0, uint32_t& r1, uint32_t& r2, uint32_t& r3,
                                      uint32_t addr) {
    asm volatile("ldmatrix.sync.aligned.m8n8.x4.shared.b16 {%0,%1,%2,%3}, [%4];\n"
                 : "=r"(r0), "=r"(r1), "=r"(r2), "=r"(r3) : "r"(addr));
}
__device__ __forceinline__ void ldsm4t(uint32_t& r0, uint32_t& r1, uint32_t& r2, uint32_t& r3,
                                       uint32_t addr) {
    asm volatile("ldmatrix.sync.aligned.m8n8.x4.trans.shared.b16 {%0,%1,%2,%3}, [%4];\n"
                 : "=r"(r0), "=r"(r1), "=r"(r2), "=r"(r3) : "r"(addr));
}
__device__ __forceinline__ void mma_f16(float* d, uint32_t a0, uint32_t a1, uint32_t a2,
                                        uint32_t a3, uint32_t b0, uint32_t b1) {
    asm volatile("mma.sync.aligned.m16n8k16.row.col.f32.f16.f16.f32 "
                 "{%0,%1,%2,%3}, {%4,%5,%6,%7}, {%8,%9}, {%0,%1,%2,%3};\n"
                 : "+f"(d[0]), "+f"(d[1]), "+f"(d[2]), "+f"(d[3])
                 : "r"(a0), "r"(a1), "r"(a2), "r"(a3), "r"(b0), "r"(b1));
}

// ---------------- shared tile constants (256x128 block, 8 warps 64x64) ------
#define SROWB 80
#define ABUF  (256*SROWB)        // 20480 B
#define BBUF  (128*SROWB)        // 10240 B
#define STAGE1B (ABUF + BBUF)    // A|B = 30720
#define GEMM3S_SMEM (3*STAGE1B)  // 92160 (3-stage)

#define GEMM_ISSUE(s) do {                                                       \
    const uint32_t so = (uint32_t)(((s) % 3) * STAGE1B);                         \
    const size_t off = (size_t)(s) * 32;                                         \
    _Pragma("unroll")                                                            \
    for (int c = 0; c < 4; c++) cp16(aD + so + c * 16, A + aG + off + c * 8);    \
    cp16(bD + so,      B + bG + off);                                            \
    cp16(bD + so + 16, B + bG + off + 8);                                        \
    cp_commit();                                                                 \
} while (0)

// ---------------- fused Q+KV fp16 GEMM: fp16 out, 3-stage --------------------
__global__ __launch_bounds__(256, 1) void gemm_qkv_kernel(
    const __half* __restrict__ Aq, const __half* __restrict__ Ax,
    const __half* __restrict__ Bq, const __half* __restrict__ Bkv,
    __half* __restrict__ Cq, __half* __restrict__ Ckv) {
    extern __shared__ char smem[];
    const uint32_t sb = (uint32_t)__cvta_generic_to_shared(smem);
    const int tid = threadIdx.x;
    const int lane = tid & 31, wid = tid >> 5;
    const int warpM = wid >> 1, warpN = wid & 1;

    const bool isQ = blockIdx.x < 16;
    const __half* A = isQ ? Aq : Ax;
    const __half* B = isQ ? Bq : Bkv;
    __half* C = isQ ? Cq : Ckv;
    const int N = isQ ? DIMD : KVF;
    const int K = DIMD;
    const int mBlk = blockIdx.y * 256;
    const int nBlk = (isQ ? blockIdx.x : (blockIdx.x - 16)) * 128;

    const size_t aG = (size_t)(mBlk + tid) * K;
    const int brow = tid >> 1, bc0 = (tid & 1) * 2;
    const size_t bG = (size_t)(nBlk + brow) * K + bc0 * 8;
    const uint32_t aD = sb + tid * SROWB;
    const uint32_t bD = sb + ABUF + brow * SROWB + bc0 * 16;

    const int aRow = warpM * 64 + (lane & 7) + ((lane >> 3) & 1) * 8;
    const uint32_t aLd = aRow * SROWB + (lane >> 4) * 16;
    const int bRow = warpN * 64 + (lane & 7) + (lane >> 4) * 8;
    const uint32_t bLd = bRow * SROWB + ((lane >> 3) & 1) * 16;

    float acc[4][8][4];
#pragma unroll
    for (int i = 0; i < 4; i++)
#pragma unroll
        for (int j = 0; j < 8; j++)
#pragma unroll
            for (int r = 0; r < 4; r++) acc[i][j][r] = 0.f;

    const int nkt = K / 32;
    GEMM_ISSUE(0);
    GEMM_ISSUE(1);

    for (int kt = 0; kt < nkt; kt++) {
        if (kt < nkt - 1) cp_wait1(); else cp_wait0();
        __syncthreads();
        if (kt + 2 < nkt) GEMM_ISSUE(kt + 2);

        const uint32_t base = sb + (uint32_t)((kt % 3) * STAGE1B);
#pragma unroll
        for (int kkB = 0; kkB < 64; kkB += 32) {
            uint32_t bh[16];
#pragma unroll
            for (int g = 0; g < 4; g++)
                ldsm4(bh[4*g], bh[4*g+1], bh[4*g+2], bh[4*g+3],
                      base + ABUF + bLd + kkB + (uint32_t)(g * 16 * SROWB));
#pragma unroll
            for (int i = 0; i < 4; i++) {
                uint32_t ah[4];
                ldsm4(ah[0], ah[1], ah[2], ah[3],
                      base + aLd + (uint32_t)(i * 16 * SROWB) + kkB);
#pragma unroll
                for (int j = 0; j < 8; j++)
                    mma_f16(acc[i][j], ah[0], ah[1], ah[2], ah[3], bh[2*j], bh[2*j+1]);
            }
        }
    }

#pragma unroll
    for (int i = 0; i < 4; i++) {
#pragma unroll
        for (int j = 0; j < 8; j++) {
            int rg = mBlk + warpM * 64 + i * 16 + (lane >> 2);
            int cg = nBlk + warpN * 64 + j * 8 + (lane & 3) * 2;
            *(uint32_t*)(C + (size_t)rg * N + cg) =
                pack_h2(__float2half_rn(acc[i][j][0]), __float2half_rn(acc[i][j][1]));
            *(uint32_t*)(C + (size_t)(rg + 8) * N + cg) =
                pack_h2(__float2half_rn(acc[i][j][2]), __float2half_rn(acc[i][j][3]));
        }
    }
}

// ---------------- Wo GEMM: fp32 out + bias, 3-stage --------------------------
__global__ __launch_bounds__(256, 1) void gemm_out_kernel(
    const __half* __restrict__ A, const __half* __restrict__ B,
    const float* __restrict__ bias, float* __restrict__ C) {
    extern __shared__ char smem[];
    const uint32_t sb = (uint32_t)__cvta_generic_to_shared(smem);
    const int tid = threadIdx.x;
    const int lane = tid & 31, wid = tid >> 5;
    const int warpM = wid >> 1, warpN = wid & 1;
    const int N = DIMD, K = DIMD;
    const int mBlk = blockIdx.y * 256, nBlk = blockIdx.x * 128;

    const size_t aG = (size_t)(mBlk + tid) * K;
    const int brow = tid >> 1, bc0 = (tid & 1) * 2;
    const size_t bG = (size_t)(nBlk + brow) * K + bc0 * 8;
    const uint32_t aD = sb + tid * SROWB;
    const uint32_t bD = sb + ABUF + brow * SROWB + bc0 * 16;

    const int aRow = warpM * 64 + (lane & 7) + ((lane >> 3) & 1) * 8;
    const uint32_t aLd = aRow * SROWB + (lane >> 4) * 16;
    const int bRow = warpN * 64 + (lane & 7) + (lane >> 4) * 8;
    const uint32_t bLd = bRow * SROWB + ((lane >> 3) & 1) * 16;

    float acc[4][8][4];
#pragma unroll
    for (int i = 0; i < 4; i++)
#pragma unroll
        for (int j = 0; j < 8; j++)
#pragma unroll
            for (int r = 0; r < 4; r++) acc[i][j][r] = 0.f;

    const int nkt = K / 32;
    GEMM_ISSUE(0);
    GEMM_ISSUE(1);

    for (int kt = 0; kt < nkt; kt++) {
        if (kt < nkt - 1) cp_wait1(); else cp_wait0();
        __syncthreads();
        if (kt + 2 < nkt) GEMM_ISSUE(kt + 2);

        const uint32_t base = sb + (uint32_t)((kt % 3) * STAGE1B);
#pragma unroll
        for (int kkB = 0; kkB < 64; kkB += 32) {
            uint32_t bh[16];
#pragma unroll
            for (int g = 0; g < 4; g++)
                ldsm4(bh[4*g], bh[4*g+1], bh[4*g+2], bh[4*g+3],
                      base + ABUF + bLd + kkB + (uint32_t)(g * 16 * SROWB));
#pragma unroll
            for (int i = 0; i < 4; i++) {
                uint32_t ah[4];
                ldsm4(ah[0], ah[1], ah[2], ah[3],
                      base + aLd + (uint32_t)(i * 16 * SROWB) + kkB);
#pragma unroll
                for (int j = 0; j < 8; j++)
                    mma_f16(acc[i][j], ah[0], ah[1], ah[2], ah[3], bh[2*j], bh[2*j+1]);
            }
        }
    }

#pragma unroll
    for (int i = 0; i < 4; i++) {
#pragma unroll
        for (int j = 0; j < 8; j++) {
            int rg = mBlk + warpM * 64 + i * 16 + (lane >> 2);
            int cg = nBlk + warpN * 64 + j * 8 + (lane & 3) * 2;
            float b0 = bias[cg], b1 = bias[cg + 1];
            *(float2*)(C + (size_t)rg * N + cg) =
                make_float2(acc[i][j][0] + b0, acc[i][j][1] + b1);
            *(float2*)(C + (size_t)(rg + 8) * N + cg) =
                make_float2(acc[i][j][2] + b0, acc[i][j][3] + b1);
        }
    }
}

// ---------------- vmean: global query rows (i<64) -> fp16 at ----------------
__global__ __launch_bounds__(1024) void vmean_kernel(const __half* __restrict__ kv,
                                                     __half* __restrict__ at16) {
    int b = blockIdx.x >> 2, kvh = blockIdx.x & 3;
    int d = threadIdx.x & 127;
    int c = threadIdx.x >> 7;
    const __half* v = kv + (size_t)b * SB * KVF + NKVH * HD + kvh * HD + d;
    float s = 0.f;
    int j0 = c * 256;
#pragma unroll 8
    for (int j = j0; j < j0 + 256; j++) s += __half2float(v[(size_t)j * KVF]);
    __shared__ float red[8][128];
    red[c][d] = s;
    __syncthreads();
    if (c == 0) {
        float t = 0.f;
#pragma unroll
        for (int u = 0; u < 8; u++) t += red[u][d];
        __half th = __float2half_rn(t * (1.0f / 2048.0f));
        for (int hh = 0; hh < 4; hh++) {
            int h = kvh * 4 + hh;
            for (int i = 0; i < 64; i++)
                at16[((size_t)(b * SB) + i) * DIMD + h * HD + d] = th;
        }
    }
}

// ---------------- fp16 tensor-core flash attention (R14 version) ------------
// smem tiles (fp16, ASTR=136 halfs/row): Q | K | V
#define ASTR 136
#define ATILE (64*ASTR)
#define AQ  0
#define AK  (ATILE*2)
#define AV  (2*ATILE*2)
#define ATTN_SMEM_BYTES (3*ATILE*2)   // 52224

__global__ __launch_bounds__(128) void attn_mma_kernel(
    const __half* __restrict__ q, const __half* __restrict__ kv,
    __half* __restrict__ at16) {
    extern __shared__ char asmem[];
    __half* sB = (__half*)asmem;
    const uint32_t sb = (uint32_t)__cvta_generic_to_shared(asmem);

    const int tid = threadIdx.x;
    const int lane = tid & 31, w = tid >> 5;
    const int i0 = 64 + blockIdx.x * 64;
    const int h  = blockIdx.y;
    const int b  = blockIdx.z;
    const int kvh = h >> 2;
    const float slope = exp2f(-0.5f * (float)(h + 1));
    const float scale = 0.08838834764831845f;

    const __half* qbase = q  + ((size_t)(b * SB + i0) * DIMD) + h * HD;
    const __half* kbase = kv + ((size_t)b * SB * KVF) + kvh * HD;
    const __half* vbase = kbase + NKVH * HD;

    // load Q tile (already fp16 — straight copy)
#pragma unroll
    for (int it = 0; it < 8; it++) {
        int flat = it * 1024 + tid * 8;
        int r = flat >> 7, c = flat & 127;
        *(uint4*)(sB + (AQ/2) + r * ASTR + c) = *(const uint4*)(qbase + (size_t)r * DIMD + c);
    }

    const uint32_t aOff = (uint32_t)((w * 16 + (lane & 7) + ((lane >> 3) & 1) * 8) * 272
                                     + (lane >> 4) * 16);
    const uint32_t bRowOff = (uint32_t)(((lane & 7) + (lane >> 4) * 8) * 272
                                        + ((lane >> 3) & 1) * 16);
    const uint32_t vOff = (uint32_t)(((lane & 7) + ((lane >> 3) & 1) * 8) * 272
                                     + (lane >> 4) * 16);

    const int gi0 = i0 + w * 16 + (lane >> 2);
    const int gi1 = gi0 + 8;
    const int cb  = (lane & 3) * 2;
    float m0 = -INFINITY, m1 = -INFINITY, l0 = 0.f, l1 = 0.f;

    float o[16][4];
#pragma unroll
    for (int f = 0; f < 16; f++)
#pragma unroll
        for (int r = 0; r < 4; r++) o[f][r] = 0.f;

    for (int j0t = 64; j0t < SB; j0t += 64) {
        int mdist = max(abs(i0 - (j0t + 63)), abs((i0 + 63) - j0t));
        if (mdist <= 256) continue;

        __syncthreads();
        // load K and V tiles (already fp16 — straight copies)
#pragma unroll
        for (int it = 0; it < 8; it++) {
            int flat = it * 1024 + tid * 8;
            int r = flat >> 7, c = flat & 127;
            *(uint4*)(sB + (AK/2) + r * ASTR + c) =
                *(const uint4*)(kbase + (size_t)(j0t + r) * KVF + c);
            *(uint4*)(sB + (AV/2) + r * ASTR + c) =
                *(const uint4*)(vbase + (size_t)(j0t + r) * KVF + c);
        }
        __syncthreads();

        // ---- S = Q K^T ----
        float sacc[8][4];
#pragma unroll
        for (int j = 0; j < 8; j++)
#pragma unroll
            for (int r = 0; r < 4; r++) sacc[j][r] = 0.f;

#pragma unroll
        for (int kk = 0; kk < 8; kk++) {
            uint32_t qf[4];
            ldsm4(qf[0], qf[1], qf[2], qf[3], sb + AQ + aOff + kk * 32);
#pragma unroll
            for (int g = 0; g < 4; g++) {
                uint32_t kf[4];
                ldsm4(kf[0], kf[1], kf[2], kf[3],
                      sb + AK + bRowOff + (uint32_t)(g * 16 * 272) + kk * 32);
                mma_f16(sacc[2*g],   qf[0], qf[1], qf[2], qf[3], kf[0], kf[1]);
                mma_f16(sacc[2*g+1], qf[0], qf[1], qf[2], qf[3], kf[2], kf[3]);
            }
        }

        // ---- mask + ALiBi + online softmax (fp32) ----
        float tmax0 = -INFINITY, tmax1 = -INFINITY;
#pragma unroll
        for (int j = 0; j < 8; j++) {
            int gj = j0t + j * 8 + cb;
#pragma unroll
            for (int e = 0; e < 4; e++) {
                int gi = (e < 2) ? gi0 : gi1;
                int dist = abs(gi - (gj + (e & 1)));
                float val = (dist <= 256) ? -1e9f
                                          : (sacc[j][e] * scale - slope * (float)dist);
                sacc[j][e] = val;
                if (e < 2) tmax0 = fmaxf(tmax0, val);
                else       tmax1 = fmaxf(tmax1, val);
            }
        }
        tmax0 = fmaxf(tmax0, __shfl_xor_sync(0xffffffffu, tmax0, 1));
        tmax0 = fmaxf(tmax0, __shfl_xor_sync(0xffffffffu, tmax0, 2));
        tmax1 = fmaxf(tmax1, __shfl_xor_sync(0xffffffffu, tmax1, 1));
        tmax1 = fmaxf(tmax1, __shfl_xor_sync(0xffffffffu, tmax1, 2));

        float mn0 = fmaxf(m0, tmax0), mn1 = fmaxf(m1, tmax1);
        float f0 = __expf(m0 - mn0), f1 = __expf(m1 - mn1);
        float rs0 = 0.f, rs1 = 0.f;
#pragma unroll
        for (int j = 0; j < 8; j++) {
            float p0 = __expf(sacc[j][0] - mn0);
            float p1 = __expf(sacc[j][1] - mn0);
            float p2 = __expf(sacc[j][2] - mn1);
            float p3 = __expf(sacc[j][3] - mn1);
            sacc[j][0] = p0; sacc[j][1] = p1; sacc[j][2] = p2; sacc[j][3] = p3;
            rs0 += p0 + p1; rs1 += p2 + p3;
        }
        rs0 += __shfl_xor_sync(0xffffffffu, rs0, 1);
        rs0 += __shfl_xor_sync(0xffffffffu, rs0, 2);
        rs1 += __shfl_xor_sync(0xffffffffu, rs1, 1);
        rs1 += __shfl_xor_sync(0xffffffffu, rs1, 2);
        l0 = l0 * f0 + rs0; l1 = l1 * f1 + rs1;
        m0 = mn0; m1 = mn1;

#pragma unroll
        for (int f = 0; f < 16; f++) {
            o[f][0] *= f0; o[f][1] *= f0;
            o[f][2] *= f1; o[f][3] *= f1;
        }

        // ---- O += P V ----
#pragma unroll
        for (int kk = 0; kk < 4; kk++) {
            uint32_t pF[4];
            pF[0] = pack_h2(__float2half_rn(sacc[2*kk][0]),   __float2half_rn(sacc[2*kk][1]));
            pF[1] = pack_h2(__float2half_rn(sacc[2*kk][2]),   __float2half_rn(sacc[2*kk][3]));
            pF[2] = pack_h2(__float2half_rn(sacc[2*kk+1][0]), __float2half_rn(sacc[2*kk+1][1]));
            pF[3] = pack_h2(__float2half_rn(sacc[2*kk+1][2]), __float2half_rn(sacc[2*kk+1][3]));
#pragma unroll
            for (int g = 0; g < 8; g++) {
                uint32_t vh[4];
                ldsm4t(vh[0], vh[1], vh[2], vh[3],
                       sb + AV + vOff + (uint32_t)(kk * 16 * 272) + (uint32_t)(g * 32));
                mma_f16(o[2*g],   pF[0], pF[1], pF[2], pF[3], vh[0], vh[1]);
                mma_f16(o[2*g+1], pF[0], pF[1], pF[2], pF[3], vh[2], vh[3]);
            }
        }
    }

    // epilogue: divide by l, write single fp16
    float inv0 = 1.f / l0, inv1 = 1.f / l1;
    size_t row0 = (size_t)(b * SB) + gi0;
    size_t row1 = (size_t)(b * SB) + gi1;
#pragma unroll
    for (int f = 0; f < 16; f++) {
        int cg = h * HD + f * 8 + cb;
        *(uint32_t*)(at16 + row0 * DIMD + cg) =
            pack_h2(__float2half_rn(o[f][0] * inv0), __float2half_rn(o[f][1] * inv0));
        *(uint32_t*)(at16 + row1 * DIMD + cg) =
            pack_h2(__float2half_rn(o[f][2] * inv1), __float2half_rn(o[f][3] * inv1));
    }
}

// ---------------- launcher ----------------
extern "C" void kernel_launch(void* const* d_in, const int* in_sizes, int n_in,
                              void* d_out, int out_size) {
    (void)in_sizes; (void)n_in; (void)out_size;
    const float* x   = (const float*)d_in[0];
    const float* Wq  = (const float*)d_in[1];
    const float* Wkv = (const float*)d_in[2];
    const float* Wo  = (const float*)d_in[3];
    const float* bo  = (const float*)d_in[4];
    float* out = (float*)d_out;

    __half *q16, *kv16, *xq16, *x16, *at16, *wq16, *wkv16, *wo16;
    cudaGetSymbolAddress((void**)&q16,   g_q16);
    cudaGetSymbolAddress((void**)&kv16,  g_kv16);
    cudaGetSymbolAddress((void**)&xq16,  g_xq16);
    cudaGetSymbolAddress((void**)&x16,   g_x16);
    cudaGetSymbolAddress((void**)&at16,  g_at16);
    cudaGetSymbolAddress((void**)&wq16,  g_wq16);
    cudaGetSymbolAddress((void**)&wkv16, g_wkv16);
    cudaGetSymbolAddress((void**)&wo16,  g_wo16);

    cudaFuncSetAttribute(attn_mma_kernel, cudaFuncAttributeMaxDynamicSharedMemorySize,
                         ATTN_SMEM_BYTES);
    cudaFuncSetAttribute(gemm_qkv_kernel, cudaFuncAttributeMaxDynamicSharedMemorySize,
                         GEMM3S_SMEM);
    cudaFuncSetAttribute(gemm_out_kernel, cudaFuncAttributeMaxDynamicSharedMemorySize,
                         GEMM3S_SMEM);

    // gating + fused weight transposes
    gate_h_kernel<<<ROWS, 256>>>(x, xq16, x16);
    transpose_all_kernel<<<dim3(160, 64), dim3(32, 8)>>>(Wq, Wkv, Wo, wq16, wkv16, wo16);

    // fused Q + KV projection (fp16 outputs)
    gemm_qkv_kernel<<<dim3(24, ROWS/256), 256, GEMM3S_SMEM>>>(
        xq16, x16, wq16, wkv16, q16, kv16);

    // attention (fp16 in, fp16 out) — R14 configuration
    vmean_kernel<<<BATCH * NKVH, 1024>>>(kv16, at16);
    dim3 ga(31, NH, BATCH);
    attn_mma_kernel<<<ga, 128, ATTN_SMEM_BYTES>>>(q16, kv16, at16);

    // output projection (fp32 out + bias)
    gemm_out_kernel<<<dim3(DIMD/128, ROWS/256), 256, GEMM3S_SMEM>>>(
        at16, wo16, bo, out);
}

// round 17
// speedup vs baseline: 1.0658x; 1.0026x over previous
#include <cuda_runtime.h>
#include <cuda_bf16.h>
#include <cuda_fp16.h>
#include <cstdint>
#include <stdint.h>
#include <math.h>

#define SB    2048
#define DIMD  2048
#define BATCH 2
#define NH    16
#define NKVH  4
#define HD    128
#define KVF   1024
#define ROWS  (BATCH*SB)   // 4096

// ---------------- scratch (device globals: allocation-free) ----------------
__device__ __half g_q16 [(size_t)ROWS*DIMD];
__device__ __half g_kv16[(size_t)ROWS*KVF];
__device__ __half g_x16 [(size_t)ROWS*DIMD];
__device__ __half g_at16[(size_t)ROWS*DIMD];
__device__ __half g_wq16 [(size_t)DIMD*DIMD];
__device__ __half g_wkv16[(size_t)KVF *DIMD];
__device__ __half g_wo16 [(size_t)DIMD*DIMD];
__device__ float  g_cw[ROWS];
__device__ float  g_vpart[64*128];

// ---------------- helpers ----------------
__device__ __forceinline__ uint32_t pack_h2(__half a, __half b) {
    __half2 t; t.x = a; t.y = b;
    return *(uint32_t*)&t;
}

// ---------------- kernel 1: complexity gate -> cw[] AND fp16 x --------------
__global__ __launch_bounds__(256) void gate_h_kernel(const float* __restrict__ x,
                                                     float* __restrict__ cw,
                                                     __half* __restrict__ xh) {
    int row = blockIdx.x;
    const float* xr = x + (size_t)row * DIMD;
    float s = 0.f;
    for (int c = threadIdx.x; c < DIMD; c += 256) s += fabsf(xr[c]);
    __shared__ float red[256];
    red[threadIdx.x] = s; __syncthreads();
    for (int off = 128; off > 0; off >>= 1) {
        if (threadIdx.x < off) red[threadIdx.x] += red[threadIdx.x + off];
        __syncthreads();
    }
    if (threadIdx.x == 0) cw[row] = 1.f / (1.f + __expf(-red[0]));
    size_t base = (size_t)row * DIMD;
    for (int c = threadIdx.x; c < DIMD; c += 256)
        xh[base + c] = __float2half_rn(xr[c]);
}

// ------- fused transpose: Wq|Wkv|Wo [K][N] -> T[N][K], single fp16 ---------
__global__ __launch_bounds__(256) void transpose_all_kernel(
    const float* __restrict__ Wq, const float* __restrict__ Wkv,
    const float* __restrict__ Wo,
    __half* __restrict__ Tq, __half* __restrict__ Tkv, __half* __restrict__ To) {
    __shared__ float tile[32][33];
    const float* W; __half* T; int N;
    int bx = blockIdx.x;
    if (bx < 64)      { W = Wq;  T = Tq;  N = DIMD; }
    else if (bx < 96) { W = Wkv; T = Tkv; N = KVF;  bx -= 64; }
    else              { W = Wo;  T = To;  N = DIMD; bx -= 96; }
    const int K = DIMD;
    int n0 = bx * 32, k0 = blockIdx.y * 32;
    int tx = threadIdx.x, ty = threadIdx.y;
#pragma unroll
    for (int r = ty; r < 32; r += 8)
        tile[r][tx] = W[(size_t)(k0 + r) * N + n0 + tx];
    __syncthreads();
#pragma unroll
    for (int r = ty; r < 32; r += 8)
        T[(size_t)(n0 + r) * K + k0 + tx] = __float2half_rn(tile[tx][r]);
}

// ---------------- mma primitives ----------------
__device__ __forceinline__ void cp16(uint32_t dst, const void* src) {
    asm volatile("cp.async.cg.shared.global [%0], [%1], 16;\n" :: "r"(dst), "l"(src));
}
__device__ __forceinline__ void cp_commit() { asm volatile("cp.async.commit_group;\n"); }
__device__ __forceinline__ void cp_wait1() { asm volatile("cp.async.wait_group 1;\n"); }
__device__ __forceinline__ void cp_wait0() { asm volatile("cp.async.wait_group 0;\n"); }
__device__ __forceinline__ void ldsm4(uint32_t& r0, uint32_t& r1, uint32_t& r2, uint32_t& r3,
                                      uint32_t addr) {
    asm volatile("ldmatrix.sync.aligned.m8n8.x4.shared.b16 {%0,%1,%2,%3}, [%4];\n"
                 : "=r"(r0), "=r"(r1), "=r"(r2), "=r"(r3) : "r"(addr));
}
__device__ __forceinline__ void ldsm4t(uint32_t& r0, uint32_t& r1, uint32_t& r2, uint32_t& r3,
                                       uint32_t addr) {
    asm volatile("ldmatrix.sync.aligned.m8n8.x4.trans.shared.b16 {%0,%1,%2,%3}, [%4];\n"
                 : "=r"(r0), "=r"(r1), "=r"(r2), "=r"(r3) : "r"(addr));
}
__device__ __forceinline__ void mma_f16(float* d, uint32_t a0, uint32_t a1, uint32_t a2,
                                        uint32_t a3, uint32_t b0, uint32_t b1) {
    asm volatile("mma.sync.aligned.m16n8k16.row.col.f32.f16.f16.f32 "
                 "{%0,%1,%2,%3}, {%4,%5,%6,%7}, {%8,%9}, {%0,%1,%2,%3};\n"
                 : "+f"(d[0]), "+f"(d[1]), "+f"(d[2]), "+f"(d[3])
                 : "r"(a0), "r"(a1), "r"(a2), "r"(a3), "r"(b0), "r"(b1));
}

// ---------------- shared tile constants (256x128 block, 8 warps 64x64) ------
#define SROWB 80
#define ABUF  (256*SROWB)        // 20480 B
#define BBUF  (128*SROWB)        // 10240 B
#define STAGE1B (ABUF + BBUF)    // A|B = 30720
#define GEMM3S_SMEM (3*STAGE1B)  // 92160 (3-stage)

#define GEMM_ISSUE(s) do {                                                       \
    const uint32_t so = (uint32_t)(((s) % 3) * STAGE1B);                         \
    const size_t off = (size_t)(s) * 32;                                         \
    _Pragma("unroll")                                                            \
    for (int c = 0; c < 4; c++) cp16(aD + so + c * 16, A + aG + off + c * 8);    \
    cp16(bD + so,      B + bG + off);                                            \
    cp16(bD + so + 16, B + bG + off + 8);                                        \
    cp_commit();                                                                 \
} while (0)

// ---------------- fused Q+KV fp16 GEMM: fp16 out, 3-stage --------------------
// A = x16 for ALL blocks; Q blocks scale epilogue rows by cw[row].
__global__ __launch_bounds__(256, 1) void gemm_qkv_kernel(
    const __half* __restrict__ A,
    const __half* __restrict__ Bq, const __half* __restrict__ Bkv,
    __half* __restrict__ Cq, __half* __restrict__ Ckv,
    const float* __restrict__ cw) {
    extern __shared__ char smem[];
    const uint32_t sb = (uint32_t)__cvta_generic_to_shared(smem);
    const int tid = threadIdx.x;
    const int lane = tid & 31, wid = tid >> 5;
    const int warpM = wid >> 1, warpN = wid & 1;

    const bool isQ = blockIdx.x < 16;
    const __half* B = isQ ? Bq : Bkv;
    __half* C = isQ ? Cq : Ckv;
    const int N = isQ ? DIMD : KVF;
    const int K = DIMD;
    const int mBlk = blockIdx.y * 256;
    const int nBlk = (isQ ? blockIdx.x : (blockIdx.x - 16)) * 128;

    const size_t aG = (size_t)(mBlk + tid) * K;
    const int brow = tid >> 1, bc0 = (tid & 1) * 2;
    const size_t bG = (size_t)(nBlk + brow) * K + bc0 * 8;
    const uint32_t aD = sb + tid * SROWB;
    const uint32_t bD = sb + ABUF + brow * SROWB + bc0 * 16;

    const int aRow = warpM * 64 + (lane & 7) + ((lane >> 3) & 1) * 8;
    const uint32_t aLd = aRow * SROWB + (lane >> 4) * 16;
    const int bRow = warpN * 64 + (lane & 7) + (lane >> 4) * 8;
    const uint32_t bLd = bRow * SROWB + ((lane >> 3) & 1) * 16;

    float acc[4][8][4];
#pragma unroll
    for (int i = 0; i < 4; i++)
#pragma unroll
        for (int j = 0; j < 8; j++)
#pragma unroll
            for (int r = 0; r < 4; r++) acc[i][j][r] = 0.f;

    const int nkt = K / 32;
    GEMM_ISSUE(0);
    GEMM_ISSUE(1);

    for (int kt = 0; kt < nkt; kt++) {
        if (kt < nkt - 1) cp_wait1(); else cp_wait0();
        __syncthreads();
        if (kt + 2 < nkt) GEMM_ISSUE(kt + 2);

        const uint32_t base = sb + (uint32_t)((kt % 3) * STAGE1B);
#pragma unroll
        for (int kkB = 0; kkB < 64; kkB += 32) {
            uint32_t bh[16];
#pragma unroll
            for (int g = 0; g < 4; g++)
                ldsm4(bh[4*g], bh[4*g+1], bh[4*g+2], bh[4*g+3],
                      base + ABUF + bLd + kkB + (uint32_t)(g * 16 * SROWB));
#pragma unroll
            for (int i = 0; i < 4; i++) {
                uint32_t ah[4];
                ldsm4(ah[0], ah[1], ah[2], ah[3],
                      base + aLd + (uint32_t)(i * 16 * SROWB) + kkB);
#pragma unroll
                for (int j = 0; j < 8; j++)
                    mma_f16(acc[i][j], ah[0], ah[1], ah[2], ah[3], bh[2*j], bh[2*j+1]);
            }
        }
    }

#pragma unroll
    for (int i = 0; i < 4; i++) {
        int rg = mBlk + warpM * 64 + i * 16 + (lane >> 2);
        float c0 = isQ ? cw[rg] : 1.f;
        float c1 = isQ ? cw[rg + 8] : 1.f;
#pragma unroll
        for (int j = 0; j < 8; j++) {
            int cg = nBlk + warpN * 64 + j * 8 + (lane & 3) * 2;
            *(uint32_t*)(C + (size_t)rg * N + cg) =
                pack_h2(__float2half_rn(acc[i][j][0] * c0), __float2half_rn(acc[i][j][1] * c0));
            *(uint32_t*)(C + (size_t)(rg + 8) * N + cg) =
                pack_h2(__float2half_rn(acc[i][j][2] * c1), __float2half_rn(acc[i][j][3] * c1));
        }
    }
}

// ---------------- Wo GEMM: fp32 out + bias, 3-stage --------------------------
__global__ __launch_bounds__(256, 1) void gemm_out_kernel(
    const __half* __restrict__ A, const __half* __restrict__ B,
    const float* __restrict__ bias, float* __restrict__ C) {
    extern __shared__ char smem[];
    const uint32_t sb = (uint32_t)__cvta_generic_to_shared(smem);
    const int tid = threadIdx.x;
    const int lane = tid & 31, wid = tid >> 5;
    const int warpM = wid >> 1, warpN = wid & 1;
    const int N = DIMD, K = DIMD;
    const int mBlk = blockIdx.y * 256, nBlk = blockIdx.x * 128;

    const size_t aG = (size_t)(mBlk + tid) * K;
    const int brow = tid >> 1, bc0 = (tid & 1) * 2;
    const size_t bG = (size_t)(nBlk + brow) * K + bc0 * 8;
    const uint32_t aD = sb + tid * SROWB;
    const uint32_t bD = sb + ABUF + brow * SROWB + bc0 * 16;

    const int aRow = warpM * 64 + (lane & 7) + ((lane >> 3) & 1) * 8;
    const uint32_t aLd = aRow * SROWB + (lane >> 4) * 16;
    const int bRow = warpN * 64 + (lane & 7) + (lane >> 4) * 8;
    const uint32_t bLd = bRow * SROWB + ((lane >> 3) & 1) * 16;

    float acc[4][8][4];
#pragma unroll
    for (int i = 0; i < 4; i++)
#pragma unroll
        for (int j = 0; j < 8; j++)
#pragma unroll
            for (int r = 0; r < 4; r++) acc[i][j][r] = 0.f;

    const int nkt = K / 32;
    GEMM_ISSUE(0);
    GEMM_ISSUE(1);

    for (int kt = 0; kt < nkt; kt++) {
        if (kt < nkt - 1) cp_wait1(); else cp_wait0();
        __syncthreads();
        if (kt + 2 < nkt) GEMM_ISSUE(kt + 2);

        const uint32_t base = sb + (uint32_t)((kt % 3) * STAGE1B);
#pragma unroll
        for (int kkB = 0; kkB < 64; kkB += 32) {
            uint32_t bh[16];
#pragma unroll
            for (int g = 0; g < 4; g++)
                ldsm4(bh[4*g], bh[4*g+1], bh[4*g+2], bh[4*g+3],
                      base + ABUF + bLd + kkB + (uint32_t)(g * 16 * SROWB));
#pragma unroll
            for (int i = 0; i < 4; i++) {
                uint32_t ah[4];
                ldsm4(ah[0], ah[1], ah[2], ah[3],
                      base + aLd + (uint32_t)(i * 16 * SROWB) + kkB);
#pragma unroll
                for (int j = 0; j < 8; j++)
                    mma_f16(acc[i][j], ah[0], ah[1], ah[2], ah[3], bh[2*j], bh[2*j+1]);
            }
        }
    }

#pragma unroll
    for (int i = 0; i < 4; i++) {
#pragma unroll
        for (int j = 0; j < 8; j++) {
            int rg = mBlk + warpM * 64 + i * 16 + (lane >> 2);
            int cg = nBlk + warpN * 64 + j * 8 + (lane & 3) * 2;
            float b0 = bias[cg], b1 = bias[cg + 1];
            *(float2*)(C + (size_t)rg * N + cg) =
                make_float2(acc[i][j][0] + b0, acc[i][j][1] + b1);
            *(float2*)(C + (size_t)(rg + 8) * N + cg) =
                make_float2(acc[i][j][2] + b0, acc[i][j][3] + b1);
        }
    }
}

// ---------------- vmean phase 1: partial sums over 256-row chunks -----------
__global__ __launch_bounds__(256) void vmean_part_kernel(const __half* __restrict__ kv,
                                                         float* __restrict__ part) {
    int blk = blockIdx.x;            // b*32 + kvh*8 + chunk
    int b = blk >> 5, kvh = (blk >> 3) & 3, chunk = blk & 7;
    int d = threadIdx.x & 127, c = threadIdx.x >> 7;   // c: 0..1
    const __half* v = kv + (size_t)b * SB * KVF + NKVH * HD + kvh * HD + d;
    int j0 = chunk * 256 + c * 128;
    float s = 0.f;
#pragma unroll 8
    for (int j = j0; j < j0 + 128; j++) s += __half2float(v[(size_t)j * KVF]);
    __shared__ float red[2][128];
    red[c][d] = s;
    __syncthreads();
    if (c == 0) part[blk * 128 + d] = red[0][d] + red[1][d];
}

// ---------------- vmean phase 2: combine + broadcast to at16 ----------------
__global__ __launch_bounds__(128) void vmean_fin_kernel(const float* __restrict__ part,
                                                        __half* __restrict__ at16) {
    int blk = blockIdx.x;            // b*4 + kvh
    int b = blk >> 2, kvh = blk & 3;
    int d = threadIdx.x;
    float t = 0.f;
#pragma unroll
    for (int u = 0; u < 8; u++) t += part[(blk * 8 + u) * 128 + d];
    __half th = __float2half_rn(t * (1.0f / 2048.0f));
    for (int hh = 0; hh < 4; hh++) {
        int h = kvh * 4 + hh;
        for (int i = 0; i < 64; i++)
            at16[((size_t)(b * SB) + i) * DIMD + h * HD + d] = th;
    }
}

// ---------------- fp16 tensor-core flash attention (R14 version) ------------
#define ASTR 136
#define ATILE (64*ASTR)
#define AQ  0
#define AK  (ATILE*2)
#define AV  (2*ATILE*2)
#define ATTN_SMEM_BYTES (3*ATILE*2)   // 52224

__global__ __launch_bounds__(128) void attn_mma_kernel(
    const __half* __restrict__ q, const __half* __restrict__ kv,
    __half* __restrict__ at16) {
    extern __shared__ char asmem[];
    __half* sB = (__half*)asmem;
    const uint32_t sb = (uint32_t)__cvta_generic_to_shared(asmem);

    const int tid = threadIdx.x;
    const int lane = tid & 31, w = tid >> 5;
    const int i0 = 64 + blockIdx.x * 64;
    const int h  = blockIdx.y;
    const int b  = blockIdx.z;
    const int kvh = h >> 2;
    const float slope = exp2f(-0.5f * (float)(h + 1));
    const float scale = 0.08838834764831845f;

    const __half* qbase = q  + ((size_t)(b * SB + i0) * DIMD) + h * HD;
    const __half* kbase = kv + ((size_t)b * SB * KVF) + kvh * HD;
    const __half* vbase = kbase + NKVH * HD;

#pragma unroll
    for (int it = 0; it < 8; it++) {
        int flat = it * 1024 + tid * 8;
        int r = flat >> 7, c = flat & 127;
        *(uint4*)(sB + (AQ/2) + r * ASTR + c) = *(const uint4*)(qbase + (size_t)r * DIMD + c);
    }

    const uint32_t aOff = (uint32_t)((w * 16 + (lane & 7) + ((lane >> 3) & 1) * 8) * 272
                                     + (lane >> 4) * 16);
    const uint32_t bRowOff = (uint32_t)(((lane & 7) + (lane >> 4) * 8) * 272
                                        + ((lane >> 3) & 1) * 16);
    const uint32_t vOff = (uint32_t)(((lane & 7) + ((lane >> 3) & 1) * 8) * 272
                                     + (lane >> 4) * 16);

    const int gi0 = i0 + w * 16 + (lane >> 2);
    const int gi1 = gi0 + 8;
    const int cb  = (lane & 3) * 2;
    float m0 = -INFINITY, m1 = -INFINITY, l0 = 0.f, l1 = 0.f;

    float o[16][4];
#pragma unroll
    for (int f = 0; f < 16; f++)
#pragma unroll
        for (int r = 0; r < 4; r++) o[f][r] = 0.f;

    for (int j0t = 64; j0t < SB; j0t += 64) {
        int mdist = max(abs(i0 - (j0t + 63)), abs((i0 + 63) - j0t));
        if (mdist <= 256) continue;

        __syncthreads();
#pragma unroll
        for (int it = 0; it < 8; it++) {
            int flat = it * 1024 + tid * 8;
            int r = flat >> 7, c = flat & 127;
            *(uint4*)(sB + (AK/2) + r * ASTR + c) =
                *(const uint4*)(kbase + (size_t)(j0t + r) * KVF + c);
            *(uint4*)(sB + (AV/2) + r * ASTR + c) =
                *(const uint4*)(vbase + (size_t)(j0t + r) * KVF + c);
        }
        __syncthreads();

        float sacc[8][4];
#pragma unroll
        for (int j = 0; j < 8; j++)
#pragma unroll
            for (int r = 0; r < 4; r++) sacc[j][r] = 0.f;

#pragma unroll
        for (int kk = 0; kk < 8; kk++) {
            uint32_t qf[4];
            ldsm4(qf[0], qf[1], qf[2], qf[3], sb + AQ + aOff + kk * 32);
#pragma unroll
            for (int g = 0; g < 4; g++) {
                uint32_t kf[4];
                ldsm4(kf[0], kf[1], kf[2], kf[3],
                      sb + AK + bRowOff + (uint32_t)(g * 16 * 272) + kk * 32);
                mma_f16(sacc[2*g],   qf[0], qf[1], qf[2], qf[3], kf[0], kf[1]);
                mma_f16(sacc[2*g+1], qf[0], qf[1], qf[2], qf[3], kf[2], kf[3]);
            }
        }

        float tmax0 = -INFINITY, tmax1 = -INFINITY;
#pragma unroll
        for (int j = 0; j < 8; j++) {
            int gj = j0t + j * 8 + cb;
#pragma unroll
            for (int e = 0; e < 4; e++) {
                int gi = (e < 2) ? gi0 : gi1;
                int dist = abs(gi - (gj + (e & 1)));
                float val = (dist <= 256) ? -1e9f
                                          : (sacc[j][e] * scale - slope * (float)dist);
                sacc[j][e] = val;
                if (e < 2) tmax0 = fmaxf(tmax0, val);
                else       tmax1 = fmaxf(tmax1, val);
            }
        }
        tmax0 = fmaxf(tmax0, __shfl_xor_sync(0xffffffffu, tmax0, 1));
        tmax0 = fmaxf(tmax0, __shfl_xor_sync(0xffffffffu, tmax0, 2));
        tmax1 = fmaxf(tmax1, __shfl_xor_sync(0xffffffffu, tmax1, 1));
        tmax1 = fmaxf(tmax1, __shfl_xor_sync(0xffffffffu, tmax1, 2));

        float mn0 = fmaxf(m0, tmax0), mn1 = fmaxf(m1, tmax1);
        float f0 = __expf(m0 - mn0), f1 = __expf(m1 - mn1);
        float rs0 = 0.f, rs1 = 0.f;
#pragma unroll
        for (int j = 0; j < 8; j++) {
            float p0 = __expf(sacc[j][0] - mn0);
            float p1 = __expf(sacc[j][1] - mn0);
            float p2 = __expf(sacc[j][2] - mn1);
            float p3 = __expf(sacc[j][3] - mn1);
            sacc[j][0] = p0; sacc[j][1] = p1; sacc[j][2] = p2; sacc[j][3] = p3;
            rs0 += p0 + p1; rs1 += p2 + p3;
        }
        rs0 += __shfl_xor_sync(0xffffffffu, rs0, 1);
        rs0 += __shfl_xor_sync(0xffffffffu, rs0, 2);
        rs1 += __shfl_xor_sync(0xffffffffu, rs1, 1);
        rs1 += __shfl_xor_sync(0xffffffffu, rs1, 2);
        l0 = l0 * f0 + rs0; l1 = l1 * f1 + rs1;
        m0 = mn0; m1 = mn1;

#pragma unroll
        for (int f = 0; f < 16; f++) {
            o[f][0] *= f0; o[f][1] *= f0;
            o[f][2] *= f1; o[f][3] *= f1;
        }

#pragma unroll
        for (int kk = 0; kk < 4; kk++) {
            uint32_t pF[4];
            pF[0] = pack_h2(__float2half_rn(sacc[2*kk][0]),   __float2half_rn(sacc[2*kk][1]));
            pF[1] = pack_h2(__float2half_rn(sacc[2*kk][2]),   __float2half_rn(sacc[2*kk][3]));
            pF[2] = pack_h2(__float2half_rn(sacc[2*kk+1][0]), __float2half_rn(sacc[2*kk+1][1]));
            pF[3] = pack_h2(__float2half_rn(sacc[2*kk+1][2]), __float2half_rn(sacc[2*kk+1][3]));
#pragma unroll
            for (int g = 0; g < 8; g++) {
                uint32_t vh[4];
                ldsm4t(vh[0], vh[1], vh[2], vh[3],
                       sb + AV + vOff + (uint32_t)(kk * 16 * 272) + (uint32_t)(g * 32));
                mma_f16(o[2*g],   pF[0], pF[1], pF[2], pF[3], vh[0], vh[1]);
                mma_f16(o[2*g+1], pF[0], pF[1], pF[2], pF[3], vh[2], vh[3]);
            }
        }
    }

    float inv0 = 1.f / l0, inv1 = 1.f / l1;
    size_t row0 = (size_t)(b * SB) + gi0;
    size_t row1 = (size_t)(b * SB) + gi1;
#pragma unroll
    for (int f = 0; f < 16; f++) {
        int cg = h * HD + f * 8 + cb;
        *(uint32_t*)(at16 + row0 * DIMD + cg) =
            pack_h2(__float2half_rn(o[f][0] * inv0), __float2half_rn(o[f][1] * inv0));
        *(uint32_t*)(at16 + row1 * DIMD + cg) =
            pack_h2(__float2half_rn(o[f][2] * inv1), __float2half_rn(o[f][3] * inv1));
    }
}

// ---------------- launcher ----------------
extern "C" void kernel_launch(void* const* d_in, const int* in_sizes, int n_in,
                              void* d_out, int out_size) {
    (void)in_sizes; (void)n_in; (void)out_size;
    const float* x   = (const float*)d_in[0];
    const float* Wq  = (const float*)d_in[1];
    const float* Wkv = (const float*)d_in[2];
    const float* Wo  = (const float*)d_in[3];
    const float* bo  = (const float*)d_in[4];
    float* out = (float*)d_out;

    __half *q16, *kv16, *x16, *at16, *wq16, *wkv16, *wo16;
    float *cwb, *vpart;
    cudaGetSymbolAddress((void**)&q16,   g_q16);
    cudaGetSymbolAddress((void**)&kv16,  g_kv16);
    cudaGetSymbolAddress((void**)&x16,   g_x16);
    cudaGetSymbolAddress((void**)&at16,  g_at16);
    cudaGetSymbolAddress((void**)&wq16,  g_wq16);
    cudaGetSymbolAddress((void**)&wkv16, g_wkv16);
    cudaGetSymbolAddress((void**)&wo16,  g_wo16);
    cudaGetSymbolAddress((void**)&cwb,   g_cw);
    cudaGetSymbolAddress((void**)&vpart, g_vpart);

    cudaFuncSetAttribute(attn_mma_kernel, cudaFuncAttributeMaxDynamicSharedMemorySize,
                         ATTN_SMEM_BYTES);
    cudaFuncSetAttribute(gemm_qkv_kernel, cudaFuncAttributeMaxDynamicSharedMemorySize,
                         GEMM3S_SMEM);
    cudaFuncSetAttribute(gemm_out_kernel, cudaFuncAttributeMaxDynamicSharedMemorySize,
                         GEMM3S_SMEM);

    // gating + fused weight transposes
    gate_h_kernel<<<ROWS, 256>>>(x, cwb, x16);
    transpose_all_kernel<<<dim3(160, 64), dim3(32, 8)>>>(Wq, Wkv, Wo, wq16, wkv16, wo16);

    // fused Q + KV projection (single A stream; Q epilogue scales by cw)
    gemm_qkv_kernel<<<dim3(24, ROWS/256), 256, GEMM3S_SMEM>>>(
        x16, wq16, wkv16, q16, kv16, cwb);

    // vmean (parallelized two-phase) + attention
    vmean_part_kernel<<<64, 256>>>(kv16, vpart);
    vmean_fin_kernel<<<8, 128>>>(vpart, at16);
    dim3 ga(31, NH, BATCH);
    attn_mma_kernel<<<ga, 128, ATTN_SMEM_BYTES>>>(q16, kv16, at16);

    // output projection (fp32 out + bias)
    gemm_out_kernel<<<dim3(DIMD/128, ROWS/256), 256, GEMM3S_SMEM>>>(
        at16, wo16, bo, out);
}